// round 3
// baseline (speedup 1.0000x reference)
#include <cuda_runtime.h>
#include <math.h>

// Problem constants: B=8, T=512, N=128, F=16, H=32, L=4
#define BTNH_ 16777216ull   // 8*512*128*32

// Scratch (allocation-free: static device globals)
__device__ float g_xa[16777216];
__device__ float g_xb[16777216];
__device__ float g_xres[16777216];
// pair-interleaved over node n: element (l,b,t,n,o) at
//   l*BTNH_ + (b*512+t)*4096 + (n>>1)*64 + o*2 + (n&1)
__device__ float g_tcn[4ull * 16777216ull];

// ---------------- packed f32x2 helpers ----------------
typedef unsigned long long u64;

__device__ __forceinline__ u64 ffma2(u64 a, u64 b, u64 c) {
    u64 d;
    asm("fma.rn.f32x2 %0, %1, %2, %3;" : "=l"(d) : "l"(a), "l"(b), "l"(c));
    return d;
}
__device__ __forceinline__ u64 add2(u64 a, u64 b) {
    u64 d;
    asm("add.rn.f32x2 %0, %1, %2;" : "=l"(d) : "l"(a), "l"(b));
    return d;
}
__device__ __forceinline__ u64 mul2(u64 a, u64 b) {
    u64 d;
    asm("mul.rn.f32x2 %0, %1, %2;" : "=l"(d) : "l"(a), "l"(b));
    return d;
}
__device__ __forceinline__ u64 pack2(float lo, float hi) {
    u64 d;
    asm("mov.b64 %0, {%1, %2};" : "=l"(d) : "f"(lo), "f"(hi));
    return d;
}
__device__ __forceinline__ void unpack2(u64 v, float& lo, float& hi) {
    asm("mov.b64 {%0, %1}, %2;" : "=f"(lo), "=f"(hi) : "l"(v));
}

__device__ __forceinline__ float tanh_fast(float a) {
    float t = __expf(-2.f * fabsf(a));
    float r = (1.f - t) / (1.f + t);
    return copysignf(r, a);
}
__device__ __forceinline__ float sigm_fast(float a) {
    return 1.f / (1.f + __expf(-a));
}

// ---------------------------------------------------------------------------
// K1: input projection  Xp = X @ in_w + in_b  -> split into x_a | x_b | x_res
// grid 8192 x 256 thr; each block handles 64 rows (weights amortized 8x).
// ---------------------------------------------------------------------------
__global__ void __launch_bounds__(256) k_inproj(const float* __restrict__ X,
                                                const float* __restrict__ in_w,
                                                const float* __restrict__ in_b) {
    __shared__ float sw[1536];
    __shared__ float sb[96];
    for (int i = threadIdx.x; i < 1536; i += 256) sw[i] = in_w[i];
    if (threadIdx.x < 96) sb[threadIdx.x] = in_b[threadIdx.x];
    __syncthreads();

    int o = threadIdx.x & 31;
    int rsub = threadIdx.x >> 5;
#pragma unroll
    for (int gph = 0; gph < 8; gph++) {
        int row = blockIdx.x * 64 + gph * 8 + rsub;
        const float4* xr = (const float4*)(X + (size_t)row * 16);
        float4 v0 = xr[0], v1 = xr[1], v2 = xr[2], v3 = xr[3];
        float x[16] = {v0.x, v0.y, v0.z, v0.w, v1.x, v1.y, v1.z, v1.w,
                       v2.x, v2.y, v2.z, v2.w, v3.x, v3.y, v3.z, v3.w};
        float a0 = sb[o], a1 = sb[32 + o], a2 = sb[64 + o];
#pragma unroll
        for (int f = 0; f < 16; f++) {
            float xv = x[f];
            a0 = fmaf(xv, sw[f * 96 + o], a0);
            a1 = fmaf(xv, sw[f * 96 + 32 + o], a1);
            a2 = fmaf(xv, sw[f * 96 + 64 + o], a2);
        }
        size_t p = (size_t)row * 32 + o;
        g_xa[p] = a0;
        g_xb[p] = a1;
        g_xres[p] = a2;
    }
}

// ---------------------------------------------------------------------------
// K2: all 4 layers' gated dilated causal convs as packed-f32x2 GEMMs.
// Block per bn (1024 blocks), 512 threads; tile 4tau x 8o per thread.
// Sequences stored TRANSPOSED sxT[c][16 + tau] (16 leading zeros = causal pad)
// so tau-pairs are adjacent (a-side of FFMA2). Weights stored o-DUPLICATED.
// ---------------------------------------------------------------------------
// smem float offsets
#define CV_SXA 0
#define CV_SXB 16896          // 32*528
#define CV_WA  33792          // [64][64] dup
#define CV_WB  37888
#define CV_BA  41984          // [64] dup
#define CV_BB  42048
#define CV_TOT 42112          // floats (168448 B)

template <int D>
__device__ __forceinline__ void conv_half(const float* __restrict__ S,
                                          const float* __restrict__ Wd,
                                          const float* __restrict__ Bd,
                                          int tau0, int o0, u64 acc[16]) {
#pragma unroll
    for (int u = 0; u < 8; u++) {
        u64 bq = *(const u64*)(Bd + 2 * (o0 + u));
        acc[u] = bq;
        acc[8 + u] = bq;
    }
#pragma unroll 2
    for (int c = 0; c < 32; c++) {
        const float* base = S + c * 528 + 16 + tau0;
        ulonglong2 x1 = *(const ulonglong2*)base;   // {tau0,tau0+1},{tau0+2,tau0+3}
        u64 x0a, x0b;
        if (D == 1) {
            const float* p0 = base - 1;
            x0a = pack2(p0[0], p0[1]);
            x0b = pack2(p0[2], p0[3]);
        } else if (D == 2) {
            const float* p0 = base - 2;
            x0a = *(const u64*)p0;
            x0b = *(const u64*)(p0 + 2);
        } else {
            ulonglong2 x0 = *(const ulonglong2*)(base - D);
            x0a = x0.x;
            x0b = x0.y;
        }
        const float* wr0 = Wd + c * 64 + 2 * o0;          // tap0 (x[tau-d])
        const float* wr1 = Wd + (32 + c) * 64 + 2 * o0;   // tap1 (x[tau])
#pragma unroll
        for (int q = 0; q < 4; q++) {
            ulonglong2 W0 = *(const ulonglong2*)(wr0 + q * 4);
            ulonglong2 W1 = *(const ulonglong2*)(wr1 + q * 4);
            acc[2 * q]     = ffma2(W0.x, x0a, ffma2(W1.x, x1.x, acc[2 * q]));
            acc[2 * q + 1] = ffma2(W0.y, x0a, ffma2(W1.y, x1.x, acc[2 * q + 1]));
            acc[8 + 2 * q]     = ffma2(W0.x, x0b, ffma2(W1.x, x1.y, acc[8 + 2 * q]));
            acc[8 + 2 * q + 1] = ffma2(W0.y, x0b, ffma2(W1.y, x1.y, acc[8 + 2 * q + 1]));
        }
    }
}

template <int D>
__device__ __forceinline__ void conv_layer(const float* __restrict__ sm,
                                           float* __restrict__ outbase,
                                           int tau0, int o0, int nhalf, int nslot) {
    u64 ta[16];
    conv_half<D>(sm + CV_SXA, sm + CV_WA, sm + CV_BA, tau0, o0, ta);
#pragma unroll
    for (int k = 0; k < 16; k++) {
        float lo, hi;
        unpack2(ta[k], lo, hi);
        ta[k] = pack2(tanh_fast(lo), tanh_fast(hi));
    }
    u64 sg[16];
    conv_half<D>(sm + CV_SXB, sm + CV_WB, sm + CV_BB, tau0, o0, sg);
#pragma unroll
    for (int k = 0; k < 16; k++) {
        float lo, hi;
        unpack2(sg[k], lo, hi);
        sg[k] = mul2(ta[k], pack2(sigm_fast(lo), sigm_fast(hi)));
    }
    // scatter to pair-interleaved g_tcn
#pragma unroll
    for (int p = 0; p < 2; p++) {
#pragma unroll
        for (int u = 0; u < 8; u++) {
            float lo, hi;
            unpack2(sg[p * 8 + u], lo, hi);
            int oo = (nhalf * 32 + (o0 + u)) * 2 + nslot;
            outbase[(size_t)(tau0 + 2 * p) * 4096 + oo] = lo;
            outbase[(size_t)(tau0 + 2 * p + 1) * 4096 + oo] = hi;
        }
    }
}

__global__ void __launch_bounds__(512) k_conv(const float* __restrict__ ct_w,
                                              const float* __restrict__ ct_b,
                                              const float* __restrict__ cs_w,
                                              const float* __restrict__ cs_b) {
    extern __shared__ float sm[];
    int tid = threadIdx.x;
    int bn = blockIdx.x;
    int b = bn >> 7, n = bn & 127;
    int ty = tid & 127, tx = tid >> 7;
    int tau0 = ty * 4, o0 = tx * 8;

    // zero causal pad
    {
        int c = tid >> 4, m = tid & 15;
        sm[CV_SXA + c * 528 + m] = 0.f;
        sm[CV_SXB + c * 528 + m] = 0.f;
    }
    // transposed staging of both sequences
    const float* xa = g_xa + (size_t)bn * 16384;
    const float* xb = g_xb + (size_t)bn * 16384;
    for (int i = tid; i < 4096; i += 512) {
        float4 va = ((const float4*)xa)[i];
        float4 vb = ((const float4*)xb)[i];
        int tau = i >> 3, c0 = (i & 7) * 4;
        float* pa = sm + CV_SXA + c0 * 528 + 16 + tau;
        float* pb = sm + CV_SXB + c0 * 528 + 16 + tau;
        pa[0] = va.x; pa[528] = va.y; pa[1056] = va.z; pa[1584] = va.w;
        pb[0] = vb.x; pb[528] = vb.y; pb[1056] = vb.z; pb[1584] = vb.w;
    }

    for (int l = 0; l < 4; l++) {
        __syncthreads();  // staging done / previous layer's weight readers done
        for (int i = tid; i < 2048; i += 512) {
            int row = i >> 5, o = i & 31;
            float va = ct_w[l * 2048 + i];
            float vb = cs_w[l * 2048 + i];
            sm[CV_WA + row * 64 + 2 * o] = va;
            sm[CV_WA + row * 64 + 2 * o + 1] = va;
            sm[CV_WB + row * 64 + 2 * o] = vb;
            sm[CV_WB + row * 64 + 2 * o + 1] = vb;
        }
        if (tid < 32) {
            float va = ct_b[l * 32 + tid], vb = cs_b[l * 32 + tid];
            sm[CV_BA + 2 * tid] = va; sm[CV_BA + 2 * tid + 1] = va;
            sm[CV_BB + 2 * tid] = vb; sm[CV_BB + 2 * tid + 1] = vb;
        }
        __syncthreads();
        float* outbase = g_tcn + (size_t)l * BTNH_ + (size_t)b * 512 * 4096;
        if (l == 0) conv_layer<1>(sm, outbase, tau0, o0, n >> 1, n & 1);
        else if (l == 1) conv_layer<2>(sm, outbase, tau0, o0, n >> 1, n & 1);
        else if (l == 2) conv_layer<4>(sm, outbase, tau0, o0, n >> 1, n & 1);
        else conv_layer<8>(sm, outbase, tau0, o0, n >> 1, n & 1);
    }
}

// ---------------------------------------------------------------------------
// K3: fused 4-layer GCN/residual/skip recurrence + head, packed f32x2.
// Block per (b,t) (4096 blocks), 512 threads; tile 2i x 4o per thread
// (ty = tid&63 -> i0 = 2*ty, tx = tid>>6 -> o0 = 4*tx).
// sAT: A transposed [j][i] (i-pairs adjacent). sXd: x_res o-duplicated
// [j][2o]. sT1/sT2: transposed intermediates [c][i] (row stride 132).
// Weights o-duplicated. skip accumulator packed in registers.
// ---------------------------------------------------------------------------
#define LY_SAT 0          // 128*128
#define LY_SXD 16384      // 128*64
#define LY_ST1 24576      // 32*132
#define LY_ST2 28800      // 32*132
#define LY_WG  33024      // 32*64
#define LY_WS  35072
#define LY_WR  37120
#define LY_BG  39168      // 64
#define LY_BS  39232
#define LY_BR  39296
#define LY_W1  39360      // 32*64
#define LY_W2  41408      // 32*32 (dup over 16 outs)
#define LY_B1  42432      // 64
#define LY_B2  42496      // 32
#define LY_TOT 42528      // floats (170112 B)

__global__ void __launch_bounds__(512) k_layers(
    const float* __restrict__ A, const float* __restrict__ gcn_w,
    const float* __restrict__ gcn_b, const float* __restrict__ res_w,
    const float* __restrict__ res_b, const float* __restrict__ skip_w,
    const float* __restrict__ skip_b, const float* __restrict__ out1_w,
    const float* __restrict__ out1_b, const float* __restrict__ out2_w,
    const float* __restrict__ out2_b, float* __restrict__ out) {
    extern __shared__ float sm[];
    int bt = blockIdx.x;
    int tid = threadIdx.x;
    int ty = tid & 63, tx = tid >> 6;
    int i0 = ty * 2, o0 = tx * 4;
    size_t base = (size_t)bt * 4096;

    // ---- staging ----
    for (int i = tid; i < 16384; i += 512) {
        int r = i >> 7, j = i & 127;
        sm[LY_SAT + j * 128 + r] = A[i];   // sAT[j][i] = A[i][j]
    }
    for (int i = tid; i < 4096; i += 512) {
        int r = i >> 5, o = i & 31;
        float v = g_xres[base + i];
        sm[LY_SXD + r * 64 + 2 * o] = v;
        sm[LY_SXD + r * 64 + 2 * o + 1] = v;
    }
    for (int i = tid; i < 1024; i += 512) {
        int c = i >> 5, o = i & 31;
        float v = out1_w[i];
        sm[LY_W1 + c * 64 + 2 * o] = v;
        sm[LY_W1 + c * 64 + 2 * o + 1] = v;
    }
    if (tid < 512) {
        int c = tid >> 4, o = tid & 15;
        float v = out2_w[c * 16 + o];
        sm[LY_W2 + c * 32 + 2 * o] = v;
        sm[LY_W2 + c * 32 + 2 * o + 1] = v;
    }
    if (tid < 32) {
        float v = out1_b[tid];
        sm[LY_B1 + 2 * tid] = v; sm[LY_B1 + 2 * tid + 1] = v;
    }
    if (tid < 16) {
        float v = out2_b[tid];
        sm[LY_B2 + 2 * tid] = v; sm[LY_B2 + 2 * tid + 1] = v;
    }

    u64 skipacc[4] = {0, 0, 0, 0};

    for (int l = 0; l < 4; l++) {
        __syncthreads();  // (A) staging / Xnew visible; weight readers done
        for (int i = tid; i < 1024; i += 512) {
            int c = i >> 5, o = i & 31;
            float vg = gcn_w[l * 1024 + i];
            float vs = skip_w[l * 1024 + i];
            float vr = res_w[l * 1024 + i];
            sm[LY_WG + c * 64 + 2 * o] = vg; sm[LY_WG + c * 64 + 2 * o + 1] = vg;
            sm[LY_WS + c * 64 + 2 * o] = vs; sm[LY_WS + c * 64 + 2 * o + 1] = vs;
            sm[LY_WR + c * 64 + 2 * o] = vr; sm[LY_WR + c * 64 + 2 * o + 1] = vr;
        }
        if (tid < 32) {
            float vg = gcn_b[l * 32 + tid], vs = skip_b[l * 32 + tid],
                  vr = res_b[l * 32 + tid];
            sm[LY_BG + 2 * tid] = vg; sm[LY_BG + 2 * tid + 1] = vg;
            sm[LY_BS + 2 * tid] = vs; sm[LY_BS + 2 * tid + 1] = vs;
            sm[LY_BR + 2 * tid] = vr; sm[LY_BR + 2 * tid + 1] = vr;
        }
        __syncthreads();  // (B)

        // ---- GEMM1: AX = A @ Xres ----
        u64 acc[4] = {0, 0, 0, 0};
#pragma unroll 4
        for (int j = 0; j < 128; j++) {
            u64 a2 = *(const u64*)(sm + LY_SAT + j * 128 + i0);
            ulonglong2 xA = *(const ulonglong2*)(sm + LY_SXD + j * 64 + 2 * o0);
            ulonglong2 xB = *(const ulonglong2*)(sm + LY_SXD + j * 64 + 2 * o0 + 4);
            acc[0] = ffma2(a2, xA.x, acc[0]);
            acc[1] = ffma2(a2, xA.y, acc[1]);
            acc[2] = ffma2(a2, xB.x, acc[2]);
            acc[3] = ffma2(a2, xB.y, acc[3]);
        }
#pragma unroll
        for (int u = 0; u < 4; u++)
            *(u64*)(sm + LY_ST1 + (o0 + u) * 132 + i0) = acc[u];
        __syncthreads();  // (C)

        // ---- GEMM2: h = AX @ gcn_w + gcn_b + tcn ----
        u64 h[4];
#pragma unroll
        for (int u = 0; u < 4; u++) h[u] = *(const u64*)(sm + LY_BG + 2 * (o0 + u));
#pragma unroll 4
        for (int c = 0; c < 32; c++) {
            u64 a2 = *(const u64*)(sm + LY_ST1 + c * 132 + i0);
            ulonglong2 wA = *(const ulonglong2*)(sm + LY_WG + c * 64 + 2 * o0);
            ulonglong2 wB = *(const ulonglong2*)(sm + LY_WG + c * 64 + 2 * o0 + 4);
            h[0] = ffma2(a2, wA.x, h[0]);
            h[1] = ffma2(a2, wA.y, h[1]);
            h[2] = ffma2(a2, wB.x, h[2]);
            h[3] = ffma2(a2, wB.y, h[3]);
        }
        {
            const float* tp = g_tcn + (size_t)l * BTNH_ + base + ty * 64 + 2 * o0;
            ulonglong2 t01 = *(const ulonglong2*)tp;
            ulonglong2 t23 = *(const ulonglong2*)(tp + 4);
            h[0] = add2(h[0], t01.x);
            h[1] = add2(h[1], t01.y);
            h[2] = add2(h[2], t23.x);
            h[3] = add2(h[3], t23.y);
        }
#pragma unroll
        for (int u = 0; u < 4; u++)
            *(u64*)(sm + LY_ST2 + (o0 + u) * 132 + i0) = h[u];
        __syncthreads();  // (D)

        // ---- GEMM3+4 fused: skip += h@skip_w + b;  xn = h@res_w + b + xold ----
        u64 sacc[4], racc[4];
#pragma unroll
        for (int u = 0; u < 4; u++) {
            sacc[u] = *(const u64*)(sm + LY_BS + 2 * (o0 + u));
            racc[u] = *(const u64*)(sm + LY_BR + 2 * (o0 + u));
        }
#pragma unroll 4
        for (int c = 0; c < 32; c++) {
            u64 a2 = *(const u64*)(sm + LY_ST2 + c * 132 + i0);
            ulonglong2 sA = *(const ulonglong2*)(sm + LY_WS + c * 64 + 2 * o0);
            ulonglong2 sB = *(const ulonglong2*)(sm + LY_WS + c * 64 + 2 * o0 + 4);
            ulonglong2 rA = *(const ulonglong2*)(sm + LY_WR + c * 64 + 2 * o0);
            ulonglong2 rB = *(const ulonglong2*)(sm + LY_WR + c * 64 + 2 * o0 + 4);
            sacc[0] = ffma2(a2, sA.x, sacc[0]);
            sacc[1] = ffma2(a2, sA.y, sacc[1]);
            sacc[2] = ffma2(a2, sB.x, sacc[2]);
            sacc[3] = ffma2(a2, sB.y, sacc[3]);
            racc[0] = ffma2(a2, rA.x, racc[0]);
            racc[1] = ffma2(a2, rA.y, racc[1]);
            racc[2] = ffma2(a2, rB.x, racc[2]);
            racc[3] = ffma2(a2, rB.y, racc[3]);
        }
#pragma unroll
        for (int u = 0; u < 4; u++) skipacc[u] = add2(skipacc[u], sacc[u]);
        // residual add + duplicated store (own slots only -> no race)
#pragma unroll
        for (int u = 0; u < 4; u++) {
            float xlo = sm[LY_SXD + i0 * 64 + 2 * (o0 + u)];
            float xhi = sm[LY_SXD + (i0 + 1) * 64 + 2 * (o0 + u)];
            u64 xn = add2(racc[u], pack2(xlo, xhi));
            float nlo, nhi;
            unpack2(xn, nlo, nhi);
            *(u64*)(sm + LY_SXD + i0 * 64 + 2 * (o0 + u)) = pack2(nlo, nlo);
            *(u64*)(sm + LY_SXD + (i0 + 1) * 64 + 2 * (o0 + u)) = pack2(nhi, nhi);
        }
    }

    // ---- head ----
    __syncthreads();  // GEMM3/4 readers of sT2 done
#pragma unroll
    for (int u = 0; u < 4; u++) {
        float lo, hi;
        unpack2(skipacc[u], lo, hi);
        *(u64*)(sm + LY_ST2 + (o0 + u) * 132 + i0) =
            pack2(fmaxf(lo, 0.f), fmaxf(hi, 0.f));
    }
    __syncthreads();
    u64 oacc[4];
#pragma unroll
    for (int u = 0; u < 4; u++) oacc[u] = *(const u64*)(sm + LY_B1 + 2 * (o0 + u));
#pragma unroll 4
    for (int c = 0; c < 32; c++) {
        u64 a2 = *(const u64*)(sm + LY_ST2 + c * 132 + i0);
        ulonglong2 wA = *(const ulonglong2*)(sm + LY_W1 + c * 64 + 2 * o0);
        ulonglong2 wB = *(const ulonglong2*)(sm + LY_W1 + c * 64 + 2 * o0 + 4);
        oacc[0] = ffma2(a2, wA.x, oacc[0]);
        oacc[1] = ffma2(a2, wA.y, oacc[1]);
        oacc[2] = ffma2(a2, wB.x, oacc[2]);
        oacc[3] = ffma2(a2, wB.y, oacc[3]);
    }
#pragma unroll
    for (int u = 0; u < 4; u++) {
        float lo, hi;
        unpack2(oacc[u], lo, hi);
        *(u64*)(sm + LY_ST1 + (o0 + u) * 132 + i0) =
            pack2(fmaxf(lo, 0.f), fmaxf(hi, 0.f));
    }
    __syncthreads();
    // out2: 16 outputs; o0p = tx*2
    {
        int o0p = tx * 2;
        u64 oc[2];
        oc[0] = *(const u64*)(sm + LY_B2 + 2 * o0p);
        oc[1] = *(const u64*)(sm + LY_B2 + 2 * (o0p + 1));
#pragma unroll 4
        for (int c = 0; c < 32; c++) {
            u64 a2 = *(const u64*)(sm + LY_ST1 + c * 132 + i0);
            ulonglong2 wv = *(const ulonglong2*)(sm + LY_W2 + c * 32 + 2 * o0p);
            oc[0] = ffma2(a2, wv.x, oc[0]);
            oc[1] = ffma2(a2, wv.y, oc[1]);
        }
        float* op = out + (size_t)bt * 2048;
#pragma unroll
        for (int v = 0; v < 2; v++) {
            float lo, hi;
            unpack2(oc[v], lo, hi);
            op[i0 * 16 + o0p + v] = lo;
            op[(i0 + 1) * 16 + o0p + v] = hi;
        }
    }
}

// ---------------------------------------------------------------------------
extern "C" void kernel_launch(void* const* d_in, const int* in_sizes, int n_in,
                              void* d_out, int out_size) {
    const float* X = (const float*)d_in[0];
    const float* A = (const float*)d_in[1];
    const float* in_w = (const float*)d_in[2];
    const float* in_b = (const float*)d_in[3];
    const float* ct_w = (const float*)d_in[4];
    const float* ct_b = (const float*)d_in[5];
    const float* cs_w = (const float*)d_in[6];
    const float* cs_b = (const float*)d_in[7];
    const float* gcn_w = (const float*)d_in[8];
    const float* gcn_b = (const float*)d_in[9];
    const float* res_w = (const float*)d_in[10];
    const float* res_b = (const float*)d_in[11];
    const float* skip_w = (const float*)d_in[12];
    const float* skip_b = (const float*)d_in[13];
    const float* out1_w = (const float*)d_in[14];
    const float* out1_b = (const float*)d_in[15];
    const float* out2_w = (const float*)d_in[16];
    const float* out2_b = (const float*)d_in[17];
    float* out = (float*)d_out;

    cudaFuncSetAttribute(k_conv, cudaFuncAttributeMaxDynamicSharedMemorySize,
                         CV_TOT * 4);
    cudaFuncSetAttribute(k_layers, cudaFuncAttributeMaxDynamicSharedMemorySize,
                         LY_TOT * 4);

    k_inproj<<<8192, 256>>>(X, in_w, in_b);
    k_conv<<<1024, 512, CV_TOT * 4>>>(ct_w, ct_b, cs_w, cs_b);
    k_layers<<<4096, 512, LY_TOT * 4>>>(A, gcn_w, gcn_b, res_w, res_b, skip_w,
                                        skip_b, out1_w, out1_b, out2_w, out2_b,
                                        out);
}

// round 5
// speedup vs baseline: 1.8493x; 1.8493x over previous
#include <cuda_runtime.h>
#include <math.h>

// Problem constants: B=8, T=512, N=128, F=16, H=32, L=4
#define BTNH_ 16777216ull   // 8*512*128*32

// Scratch (allocation-free: static device globals)
__device__ float g_xa[16777216];
__device__ float g_xb[16777216];
__device__ float g_xres[16777216];
__device__ float g_tcn[4ull * 16777216ull];  // [l][b][t][n][o]

// ---------------------------------------------------------------------------
// K1: input projection (round-3 form, measured 100us, passed)
// ---------------------------------------------------------------------------
__global__ void __launch_bounds__(256) k_inproj(const float* __restrict__ X,
                                                const float* __restrict__ in_w,
                                                const float* __restrict__ in_b) {
    __shared__ float sw[1536];
    __shared__ float sb[96];
    for (int i = threadIdx.x; i < 1536; i += 256) sw[i] = in_w[i];
    if (threadIdx.x < 96) sb[threadIdx.x] = in_b[threadIdx.x];
    __syncthreads();

    int o = threadIdx.x & 31;
    int rsub = threadIdx.x >> 5;
#pragma unroll
    for (int gph = 0; gph < 8; gph++) {
        int row = blockIdx.x * 64 + gph * 8 + rsub;
        const float4* xr = (const float4*)(X + (size_t)row * 16);
        float4 v0 = xr[0], v1 = xr[1], v2 = xr[2], v3 = xr[3];
        float x[16] = {v0.x, v0.y, v0.z, v0.w, v1.x, v1.y, v1.z, v1.w,
                       v2.x, v2.y, v2.z, v2.w, v3.x, v3.y, v3.z, v3.w};
        float a0 = sb[o], a1 = sb[32 + o], a2 = sb[64 + o];
#pragma unroll
        for (int f = 0; f < 16; f++) {
            float xv = x[f];
            a0 = fmaf(xv, sw[f * 96 + o], a0);
            a1 = fmaf(xv, sw[f * 96 + 32 + o], a1);
            a2 = fmaf(xv, sw[f * 96 + 64 + o], a2);
        }
        size_t p = (size_t)row * 32 + o;
        g_xa[p] = a0;
        g_xb[p] = a1;
        g_xres[p] = a2;
    }
}

// ---------------------------------------------------------------------------
// K2 v2: gated dilated causal convs, tiled 4tau x 8o per thread.
// 1024 blocks (bn), 512 threads.  ty = tid&127 -> tau0 = 4*ty,
// tx = tid>>7 -> o0 = 8*tx.
// Sequences transposed in smem: sx[c][528], 16 leading zeros (causal pad),
// data at +16+tau.  Rows are 2112B = 132*16B -> LDS.128-aligned at tau%4==0.
// Weights in natural [2][32][32] layout -> o-contiguous float4 loads; within
// a warp all lanes share o0 -> weight LDS are broadcast (conflict-free).
// Issue mix per c per conv: ~7 LDS + 64 FFMA (was 66 LDS + 64 FFMA).
// ---------------------------------------------------------------------------
#define CVX_SXA 0
#define CVX_SXB 16896          // 32*528
#define CVX_WA  33792          // [2][32][32]
#define CVX_WB  35840
#define CVX_BA  37888          // [32]
#define CVX_BB  37920
#define CVX_TOT 37952          // floats (151808 B)

template <int D>
__device__ __forceinline__ void conv8x4(const float* __restrict__ S,
                                        const float* __restrict__ W,
                                        const float* __restrict__ Bv,
                                        int tau0, int o0, float acc[32]) {
    float b0[8];
#pragma unroll
    for (int u = 0; u < 8; u++) b0[u] = Bv[o0 + u];
#pragma unroll
    for (int t = 0; t < 4; t++)
#pragma unroll
        for (int u = 0; u < 8; u++) acc[t * 8 + u] = b0[u];

#pragma unroll 4
    for (int c = 0; c < 32; c++) {
        const float* row = S + c * 528 + 16 + tau0;
        float4 x1 = *(const float4*)row;
        float xs1[4] = {x1.x, x1.y, x1.z, x1.w};
        float xs0[4];
        if (D == 1) {
            float p = row[-1];
            xs0[0] = p; xs0[1] = x1.x; xs0[2] = x1.y; xs0[3] = x1.z;
        } else if (D == 2) {
            float2 p = *(const float2*)(row - 2);
            xs0[0] = p.x; xs0[1] = p.y; xs0[2] = x1.x; xs0[3] = x1.y;
        } else {
            float4 p = *(const float4*)(row - D);
            xs0[0] = p.x; xs0[1] = p.y; xs0[2] = p.z; xs0[3] = p.w;
        }
        float4 wa = *(const float4*)(W + c * 32 + o0);           // tap0 lo
        float4 wb = *(const float4*)(W + c * 32 + o0 + 4);       // tap0 hi
        float4 va = *(const float4*)(W + 1024 + c * 32 + o0);    // tap1 lo
        float4 vb = *(const float4*)(W + 1024 + c * 32 + o0 + 4);
        float w0v[8] = {wa.x, wa.y, wa.z, wa.w, wb.x, wb.y, wb.z, wb.w};
        float w1v[8] = {va.x, va.y, va.z, va.w, vb.x, vb.y, vb.z, vb.w};
#pragma unroll
        for (int t = 0; t < 4; t++)
#pragma unroll
            for (int u = 0; u < 8; u++)
                acc[t * 8 + u] =
                    fmaf(w1v[u], xs1[t], fmaf(w0v[u], xs0[t], acc[t * 8 + u]));
    }
}

template <int D>
__device__ __forceinline__ void conv_layer(const float* __restrict__ sm,
                                           float* __restrict__ outp,
                                           int tau0, int o0) {
    float ta[32];
    conv8x4<D>(sm + CVX_SXA, sm + CVX_WA, sm + CVX_BA, tau0, o0, ta);
#pragma unroll
    for (int k = 0; k < 32; k++) {
        float t = __expf(-2.f * fabsf(ta[k]));
        float r = (1.f - t) / (1.f + t);
        ta[k] = copysignf(r, ta[k]);
    }
    float sg[32];
    conv8x4<D>(sm + CVX_SXB, sm + CVX_WB, sm + CVX_BB, tau0, o0, sg);
#pragma unroll
    for (int k = 0; k < 32; k++) {
        float s = 1.f / (1.f + __expf(-sg[k]));
        sg[k] = ta[k] * s;
    }
    // write tcn[b, tau0+t, n, o0..o0+7]  (outp pre-offset to [b,tau0,n,o0])
#pragma unroll
    for (int t = 0; t < 4; t++) {
        float* p = outp + (size_t)t * 4096;  // next tau: +N*H floats
        ((float4*)p)[0] = make_float4(sg[t * 8 + 0], sg[t * 8 + 1],
                                      sg[t * 8 + 2], sg[t * 8 + 3]);
        ((float4*)p)[1] = make_float4(sg[t * 8 + 4], sg[t * 8 + 5],
                                      sg[t * 8 + 6], sg[t * 8 + 7]);
    }
}

__global__ void __launch_bounds__(512) k_conv(const float* __restrict__ ct_w,
                                              const float* __restrict__ ct_b,
                                              const float* __restrict__ cs_w,
                                              const float* __restrict__ cs_b) {
    extern __shared__ float sm[];
    int tid = threadIdx.x;
    int bn = blockIdx.x;
    int b = bn >> 7, n = bn & 127;
    int ty = tid & 127, tx = tid >> 7;
    int tau0 = ty * 4, o0 = tx * 8;

    // zero causal pad (first 16 entries of each of 32 rows, both seqs)
    if (tid < 512) {
        int c = tid >> 4, m = tid & 15;
        sm[CVX_SXA + c * 528 + m] = 0.f;
        sm[CVX_SXB + c * 528 + m] = 0.f;
    }
    // transposed staging
    const float* xa = g_xa + (size_t)bn * 16384;
    const float* xb = g_xb + (size_t)bn * 16384;
    for (int i = tid; i < 4096; i += 512) {
        float4 va = ((const float4*)xa)[i];
        float4 vb = ((const float4*)xb)[i];
        int tau = i >> 3, c0 = (i & 7) * 4;
        float* pa = sm + CVX_SXA + c0 * 528 + 16 + tau;
        float* pb = sm + CVX_SXB + c0 * 528 + 16 + tau;
        pa[0] = va.x; pa[528] = va.y; pa[1056] = va.z; pa[1584] = va.w;
        pb[0] = vb.x; pb[528] = vb.y; pb[1056] = vb.z; pb[1584] = vb.w;
    }

    float* outp0 = g_tcn + ((size_t)((b * 512 + tau0) * 128 + n)) * 32 + o0;

    for (int l = 0; l < 4; l++) {
        __syncthreads();  // staging done / previous layer's weight readers done
        for (int i = tid; i < 2048; i += 512) {
            sm[CVX_WA + i] = ct_w[l * 2048 + i];
            sm[CVX_WB + i] = cs_w[l * 2048 + i];
        }
        if (tid < 32) {
            sm[CVX_BA + tid] = ct_b[l * 32 + tid];
            sm[CVX_BB + tid] = cs_b[l * 32 + tid];
        }
        __syncthreads();
        float* outp = outp0 + (size_t)l * BTNH_;
        if (l == 0) conv_layer<1>(sm, outp, tau0, o0);
        else if (l == 1) conv_layer<2>(sm, outp, tau0, o0);
        else if (l == 2) conv_layer<4>(sm, outp, tau0, o0);
        else conv_layer<8>(sm, outp, tau0, o0);
    }
}

// ---------------------------------------------------------------------------
// K3: fused 4-layer GCN/residual/skip recurrence + output head.
// (round-2 form verbatim — passed at 1961 total)
// ---------------------------------------------------------------------------
__global__ void __launch_bounds__(256, 2) k_layers(
    const float* __restrict__ A, const float* __restrict__ gcn_w,
    const float* __restrict__ gcn_b, const float* __restrict__ res_w,
    const float* __restrict__ res_b, const float* __restrict__ skip_w,
    const float* __restrict__ skip_b, const float* __restrict__ out1_w,
    const float* __restrict__ out1_b, const float* __restrict__ out2_w,
    const float* __restrict__ out2_b, float* __restrict__ out) {
    extern __shared__ float sm3[];
    float* sA = sm3;            // 16384
    float* sX = sm3 + 16384;    // 4096
    float* sB = sm3 + 20480;    // 4096

    int bt = blockIdx.x;
    int tid = threadIdx.x;
    int g = tid >> 5;
    int o = tid & 31;
    int row0 = g * 16;
    size_t base = (size_t)bt * 4096;

    for (int i = tid; i < 4096; i += 256) ((float4*)sA)[i] = ((const float4*)A)[i];
    for (int i = tid; i < 1024; i += 256)
        ((float4*)sX)[i] = ((const float4*)(g_xres + base))[i];
    __syncthreads();

    float skip[16];
#pragma unroll
    for (int ii = 0; ii < 16; ii++) skip[ii] = 0.f;

    for (int l = 0; l < 4; l++) {
        float acc[16];
#pragma unroll
        for (int ii = 0; ii < 16; ii++) acc[ii] = 0.f;
#pragma unroll 2
        for (int j = 0; j < 128; j += 4) {
            float x0 = sX[(j + 0) * 32 + o];
            float x1 = sX[(j + 1) * 32 + o];
            float x2 = sX[(j + 2) * 32 + o];
            float x3 = sX[(j + 3) * 32 + o];
#pragma unroll
            for (int ii = 0; ii < 16; ii++) {
                float4 a = *(const float4*)&sA[(row0 + ii) * 128 + j];
                acc[ii] = fmaf(a.x, x0, fmaf(a.y, x1, fmaf(a.z, x2, fmaf(a.w, x3, acc[ii]))));
            }
        }
#pragma unroll
        for (int ii = 0; ii < 16; ii++) sB[(row0 + ii) * 32 + o] = acc[ii];
        __syncwarp();

        float w[32];
#pragma unroll
        for (int c = 0; c < 32; c++) w[c] = __ldg(&gcn_w[l * 1024 + c * 32 + o]);
        float bq = __ldg(&gcn_b[l * 32 + o]);
        const float* tcnp = g_tcn + (size_t)l * BTNH_ + base;
        float h[16];
#pragma unroll
        for (int ii = 0; ii < 16; ii++) {
            float s = bq;
            const float* rowp = &sB[(row0 + ii) * 32];
#pragma unroll
            for (int c4 = 0; c4 < 8; c4++) {
                float4 v = *(const float4*)&rowp[c4 * 4];
                s = fmaf(v.x, w[4 * c4 + 0],
                    fmaf(v.y, w[4 * c4 + 1],
                    fmaf(v.z, w[4 * c4 + 2], fmaf(v.w, w[4 * c4 + 3], s))));
            }
            h[ii] = s + tcnp[(row0 + ii) * 32 + o];
        }
        __syncwarp();
#pragma unroll
        for (int ii = 0; ii < 16; ii++) sB[(row0 + ii) * 32 + o] = h[ii];
        __syncwarp();

#pragma unroll
        for (int c = 0; c < 32; c++) w[c] = __ldg(&skip_w[l * 1024 + c * 32 + o]);
        float bs = __ldg(&skip_b[l * 32 + o]);
#pragma unroll
        for (int ii = 0; ii < 16; ii++) {
            float s = bs;
            const float* rowp = &sB[(row0 + ii) * 32];
#pragma unroll
            for (int c4 = 0; c4 < 8; c4++) {
                float4 v = *(const float4*)&rowp[c4 * 4];
                s = fmaf(v.x, w[4 * c4 + 0],
                    fmaf(v.y, w[4 * c4 + 1],
                    fmaf(v.z, w[4 * c4 + 2], fmaf(v.w, w[4 * c4 + 3], s))));
            }
            skip[ii] += s;
        }

#pragma unroll
        for (int c = 0; c < 32; c++) w[c] = __ldg(&res_w[l * 1024 + c * 32 + o]);
        float br = __ldg(&res_b[l * 32 + o]);
        float xn[16];
#pragma unroll
        for (int ii = 0; ii < 16; ii++) {
            float s = br;
            const float* rowp = &sB[(row0 + ii) * 32];
#pragma unroll
            for (int c4 = 0; c4 < 8; c4++) {
                float4 v = *(const float4*)&rowp[c4 * 4];
                s = fmaf(v.x, w[4 * c4 + 0],
                    fmaf(v.y, w[4 * c4 + 1],
                    fmaf(v.z, w[4 * c4 + 2], fmaf(v.w, w[4 * c4 + 3], s))));
            }
            xn[ii] = s + sX[(row0 + ii) * 32 + o];
        }
        __syncthreads();
#pragma unroll
        for (int ii = 0; ii < 16; ii++) sX[(row0 + ii) * 32 + o] = xn[ii];
        __syncthreads();
    }

#pragma unroll
    for (int ii = 0; ii < 16; ii++)
        sB[(row0 + ii) * 32 + o] = fmaxf(skip[ii], 0.f);
    __syncwarp();

    float w1r[32];
#pragma unroll
    for (int c = 0; c < 32; c++) w1r[c] = __ldg(&out1_w[c * 32 + o]);
    float b1 = __ldg(&out1_b[o]);
    float h2[16];
#pragma unroll
    for (int ii = 0; ii < 16; ii++) {
        float s = b1;
        const float* rowp = &sB[(row0 + ii) * 32];
#pragma unroll
        for (int c4 = 0; c4 < 8; c4++) {
            float4 v = *(const float4*)&rowp[c4 * 4];
            s = fmaf(v.x, w1r[4 * c4 + 0],
                fmaf(v.y, w1r[4 * c4 + 1],
                fmaf(v.z, w1r[4 * c4 + 2], fmaf(v.w, w1r[4 * c4 + 3], s))));
        }
        h2[ii] = fmaxf(s, 0.f);
    }
    __syncwarp();
#pragma unroll
    for (int ii = 0; ii < 16; ii++) sB[(row0 + ii) * 32 + o] = h2[ii];
    __syncwarp();

    if (o < 16) {
        float w2r[32];
#pragma unroll
        for (int c = 0; c < 32; c++) w2r[c] = __ldg(&out2_w[c * 16 + o]);
        float b2 = __ldg(&out2_b[o]);
        float* op = out + (size_t)bt * 2048;
#pragma unroll
        for (int ii = 0; ii < 16; ii++) {
            float s = b2;
            const float* rowp = &sB[(row0 + ii) * 32];
#pragma unroll
            for (int c4 = 0; c4 < 8; c4++) {
                float4 v = *(const float4*)&rowp[c4 * 4];
                s = fmaf(v.x, w2r[4 * c4 + 0],
                    fmaf(v.y, w2r[4 * c4 + 1],
                    fmaf(v.z, w2r[4 * c4 + 2], fmaf(v.w, w2r[4 * c4 + 3], s))));
            }
            op[(row0 + ii) * 16 + o] = s;
        }
    }
}

// ---------------------------------------------------------------------------
extern "C" void kernel_launch(void* const* d_in, const int* in_sizes, int n_in,
                              void* d_out, int out_size) {
    const float* X = (const float*)d_in[0];
    const float* A = (const float*)d_in[1];
    const float* in_w = (const float*)d_in[2];
    const float* in_b = (const float*)d_in[3];
    const float* ct_w = (const float*)d_in[4];
    const float* ct_b = (const float*)d_in[5];
    const float* cs_w = (const float*)d_in[6];
    const float* cs_b = (const float*)d_in[7];
    const float* gcn_w = (const float*)d_in[8];
    const float* gcn_b = (const float*)d_in[9];
    const float* res_w = (const float*)d_in[10];
    const float* res_b = (const float*)d_in[11];
    const float* skip_w = (const float*)d_in[12];
    const float* skip_b = (const float*)d_in[13];
    const float* out1_w = (const float*)d_in[14];
    const float* out1_b = (const float*)d_in[15];
    const float* out2_w = (const float*)d_in[16];
    const float* out2_b = (const float*)d_in[17];
    float* out = (float*)d_out;

    cudaFuncSetAttribute(k_conv, cudaFuncAttributeMaxDynamicSharedMemorySize,
                         CVX_TOT * 4);
    cudaFuncSetAttribute(k_layers, cudaFuncAttributeMaxDynamicSharedMemorySize,
                         24576 * 4);

    k_inproj<<<8192, 256>>>(X, in_w, in_b);
    k_conv<<<1024, 512, CVX_TOT * 4>>>(ct_w, ct_b, cs_w, cs_b);
    k_layers<<<4096, 256, 24576 * 4>>>(A, gcn_w, gcn_b, res_w, res_b, skip_w,
                                       skip_b, out1_w, out1_b, out2_w, out2_b,
                                       out);
}